// round 1
// baseline (speedup 1.0000x reference)
#include <cuda_runtime.h>
#include <math.h>

// ---------------------------------------------------------------------------
// ViTBlockQuantum: analytic collapse of the 8-qubit VQC.
//   For angles phi_w = in_w + theta_w (RX gates merge), after the CNOT ring:
//     z_k = prod_{w=0..k} cos(phi_w)   (k = 1..7)
//     z_0 = prod_{w=1..7} cos(phi_w)
// ---------------------------------------------------------------------------

#define EGS 8
#define SSEQ 256
#define NHEADS 2
#define DK 4
// 0.5 (1/sqrt(dk)) * log2(e), folded into Q so softmax uses ex2 directly
#define QSCALE 0.72134752044448170368f

__device__ float g_ctx[64 * 256 * 8];  // scratch: ctx tokens (B*S*E)

__device__ __forceinline__ float ex2f(float x) {
    float y;
    asm("ex2.approx.ftz.f32 %0, %1;" : "=f"(y) : "f"(x));
    return y;
}

// angles a[8] -> z[8] per the analytic formula
__device__ __forceinline__ void vqc8(const float a[8], float z[8]) {
    float c[8];
#pragma unroll
    for (int w = 0; w < 8; w++) c[w] = __cosf(a[w]);
    // prefix products z_k = c0*...*ck for k>=1
    float p = c[0];
#pragma unroll
    for (int k = 1; k < 8; k++) { p *= c[k]; z[k] = p; }
    // z0 = c1*...*c7
    float q = c[1];
#pragma unroll
    for (int w = 2; w < 8; w++) q *= c[w];
    z[0] = q;
}

// ---------------------------------------------------------------------------
// Kernel 1: per (batch, head) block. Compute per-token Q/K/V head slices via
// the analytic VQC, then attention (no-max softmax: scores bounded in [-2,2]).
// grid = B*NHEADS, block = SSEQ threads (one q row per thread).
// ---------------------------------------------------------------------------
__global__ void __launch_bounds__(SSEQ) qkv_attn_kernel(
    const float* __restrict__ x,
    const float* __restrict__ Wq,
    const float* __restrict__ Wk,
    const float* __restrict__ Wv)
{
    __shared__ float4 Qs[SSEQ];
    __shared__ float4 Ks[SSEQ];
    __shared__ float4 Vs[SSEQ];

    const int b = blockIdx.x >> 1;
    const int h = blockIdx.x & 1;
    const int t = threadIdx.x;           // token / q row

    // load token
    const float4* xt = (const float4*)(x + (size_t)(b * SSEQ + t) * EGS);
    float4 x0 = xt[0], x1 = xt[1];
    float xi[8] = {x0.x, x0.y, x0.z, x0.w, x1.x, x1.y, x1.z, x1.w};

    float a[8], zq[8], zk[8], zv[8];
#pragma unroll
    for (int w = 0; w < 8; w++) a[w] = xi[w] + __ldg(Wq + w);
    vqc8(a, zq);
#pragma unroll
    for (int w = 0; w < 8; w++) a[w] = xi[w] + __ldg(Wk + w);
    vqc8(a, zk);
#pragma unroll
    for (int w = 0; w < 8; w++) a[w] = xi[w] + __ldg(Wv + w);
    vqc8(a, zv);

    const int hb = h * DK;
    Qs[t] = make_float4(zq[hb] * QSCALE, zq[hb + 1] * QSCALE,
                        zq[hb + 2] * QSCALE, zq[hb + 3] * QSCALE);
    Ks[t] = make_float4(zk[hb], zk[hb + 1], zk[hb + 2], zk[hb + 3]);
    Vs[t] = make_float4(zv[hb], zv[hb + 1], zv[hb + 2], zv[hb + 3]);
    __syncthreads();

    const float4 q = Qs[t];
    float sum = 0.f, c0 = 0.f, c1 = 0.f, c2 = 0.f, c3 = 0.f;
#pragma unroll 4
    for (int k = 0; k < SSEQ; k++) {
        float4 kk = Ks[k];
        float s = q.x * kk.x;
        s = fmaf(q.y, kk.y, s);
        s = fmaf(q.z, kk.z, s);
        s = fmaf(q.w, kk.w, s);
        float p = ex2f(s);
        float4 v = Vs[k];
        sum += p;
        c0 = fmaf(p, v.x, c0);
        c1 = fmaf(p, v.y, c1);
        c2 = fmaf(p, v.z, c2);
        c3 = fmaf(p, v.w, c3);
    }
    const float inv = __fdividef(1.f, sum);

    float4* co = (float4*)(g_ctx + (size_t)(b * SSEQ + t) * EGS + hb);
    *co = make_float4(c0 * inv, c1 * inv, c2 * inv, c3 * inv);
}

// ---------------------------------------------------------------------------
// Kernel 2: per-token tail. vqc(ctx,Wc) -> LN1 -> w1 matvec -> vqc(.,Wf)
// -> w2 matvec -> LN2. One token per thread.
// ---------------------------------------------------------------------------
__global__ void __launch_bounds__(256) tail_kernel(
    const float* __restrict__ x,
    const float* __restrict__ Wc,
    const float* __restrict__ Wf,
    const float* __restrict__ w1,
    const float* __restrict__ b1,
    const float* __restrict__ w2,
    const float* __restrict__ b2,
    const float* __restrict__ g1,
    const float* __restrict__ be1,
    const float* __restrict__ g2,
    const float* __restrict__ be2,
    float* __restrict__ out,
    int ntok)
{
    __shared__ float s_w1[64], s_w2[64];
    __shared__ float s_b1[8], s_b2[8], s_wc[8], s_wf[8];
    __shared__ float s_g1[8], s_be1[8], s_g2[8], s_be2[8];

    const int tid = threadIdx.x;
    if (tid < 64) { s_w1[tid] = w1[tid]; s_w2[tid] = w2[tid]; }
    if (tid < 8) {
        s_b1[tid] = b1[tid];  s_b2[tid] = b2[tid];
        s_wc[tid] = Wc[tid];  s_wf[tid] = Wf[tid];
        s_g1[tid] = g1[tid];  s_be1[tid] = be1[tid];
        s_g2[tid] = g2[tid];  s_be2[tid] = be2[tid];
    }
    __syncthreads();

    const int tok = blockIdx.x * blockDim.x + tid;
    if (tok >= ntok) return;

    // load x token + ctx token
    const float4* xt = (const float4*)(x + (size_t)tok * EGS);
    float4 x0 = xt[0], x1 = xt[1];
    float xi[8] = {x0.x, x0.y, x0.z, x0.w, x1.x, x1.y, x1.z, x1.w};
    const float4* ct = (const float4*)(g_ctx + (size_t)tok * EGS);
    float4 cA = ct[0], cB = ct[1];
    float cx[8] = {cA.x, cA.y, cA.z, cA.w, cB.x, cB.y, cB.z, cB.w};

    // attn_out = vqc(ctx, Wc)
    float a[8], ao[8];
#pragma unroll
    for (int w = 0; w < 8; w++) a[w] = cx[w] + s_wc[w];
    vqc8(a, ao);

    // y = x + attn_out ; LN1
    float y[8];
    float m = 0.f;
#pragma unroll
    for (int w = 0; w < 8; w++) { y[w] = xi[w] + ao[w]; m += y[w]; }
    m *= 0.125f;
    float var = 0.f;
#pragma unroll
    for (int w = 0; w < 8; w++) { float d = y[w] - m; var = fmaf(d, d, var); }
    var *= 0.125f;
    float r = rsqrtf(var + 1e-5f);
    float xn[8];
#pragma unroll
    for (int w = 0; w < 8; w++) xn[w] = fmaf((y[w] - m) * r, s_g1[w], s_be1[w]);

    // h = xn @ w1.T + b1
    float hh[8];
#pragma unroll
    for (int i = 0; i < 8; i++) {
        float s = s_b1[i];
#pragma unroll
        for (int j = 0; j < 8; j++) s = fmaf(xn[j], s_w1[i * 8 + j], s);
        hh[i] = s;
    }

    // hq = vqc(h, Wf)
    float hq[8];
#pragma unroll
    for (int w = 0; w < 8; w++) a[w] = hh[w] + s_wf[w];
    vqc8(a, hq);

    // ff = hq @ w2.T + b2 ; z = xn + ff ; LN2
    float z[8];
    float m2 = 0.f;
#pragma unroll
    for (int i = 0; i < 8; i++) {
        float s = s_b2[i];
#pragma unroll
        for (int j = 0; j < 8; j++) s = fmaf(hq[j], s_w2[i * 8 + j], s);
        z[i] = xn[i] + s;
        m2 += z[i];
    }
    m2 *= 0.125f;
    float v2 = 0.f;
#pragma unroll
    for (int i = 0; i < 8; i++) { float d = z[i] - m2; v2 = fmaf(d, d, v2); }
    v2 *= 0.125f;
    float r2 = rsqrtf(v2 + 1e-5f);
    float o[8];
#pragma unroll
    for (int i = 0; i < 8; i++) o[i] = fmaf((z[i] - m2) * r2, s_g2[i], s_be2[i]);

    float4* op = (float4*)(out + (size_t)tok * EGS);
    op[0] = make_float4(o[0], o[1], o[2], o[3]);
    op[1] = make_float4(o[4], o[5], o[6], o[7]);
}

extern "C" void kernel_launch(void* const* d_in, const int* in_sizes, int n_in,
                              void* d_out, int out_size)
{
    const float* x   = (const float*)d_in[0];
    const float* Wq  = (const float*)d_in[1];
    const float* Wk  = (const float*)d_in[2];
    const float* Wv  = (const float*)d_in[3];
    const float* Wc  = (const float*)d_in[4];
    const float* Wf  = (const float*)d_in[5];
    const float* w1  = (const float*)d_in[6];
    const float* b1  = (const float*)d_in[7];
    const float* w2  = (const float*)d_in[8];
    const float* b2  = (const float*)d_in[9];
    const float* g1  = (const float*)d_in[10];
    const float* be1 = (const float*)d_in[11];
    const float* g2  = (const float*)d_in[12];
    const float* be2 = (const float*)d_in[13];
    float* out = (float*)d_out;

    const int ntok = in_sizes[0] / EGS;   // B*S = 16384
    const int nb   = ntok / SSEQ;         // B = 64

    qkv_attn_kernel<<<nb * NHEADS, SSEQ>>>(x, Wq, Wk, Wv);
    tail_kernel<<<(ntok + 255) / 256, 256>>>(x, Wc, Wf, w1, b1, w2, b2,
                                             g1, be1, g2, be2, out, ntok);
}

// round 2
// speedup vs baseline: 1.3343x; 1.3343x over previous
#include <cuda_runtime.h>
#include <math.h>

// ---------------------------------------------------------------------------
// ViTBlockQuantum, fully fused. Analytic collapse of the 8-qubit VQC:
//   phi_w = in_w + theta_w;  z_k = prod_{w=0..k} cos(phi_w) (k>=1),
//   z_0 = prod_{w=1..7} cos(phi_w)
// One kernel: block = (batch, query-half), 512 threads.
//   phase 1: K,V for all 256 tokens (paired smem layout), Q for 128 queries
//   phase 2: attention, 2-way k-split, f32x2-packed (2 keys / iter)
//   phase 3: per-token tail (vqc -> LN -> matvec -> vqc -> matvec -> LN)
// ---------------------------------------------------------------------------

#define EGS 8
#define SSEQ 256
#define QH 128
// 0.5 * (1/sqrt(dk)) ... dk=4 -> 0.5 ; * log2(e) so softmax uses ex2 directly
#define QSCALE 0.72134752044448170368f

typedef unsigned long long u64;

__device__ __forceinline__ float ex2f(float x) {
    float y; asm("ex2.approx.ftz.f32 %0, %1;" : "=f"(y) : "f"(x)); return y;
}
__device__ __forceinline__ u64 pk2(float lo, float hi) {
    u64 r; asm("mov.b64 %0, {%1, %2};" : "=l"(r) : "f"(lo), "f"(hi)); return r;
}
__device__ __forceinline__ void upk2(float& lo, float& hi, u64 v) {
    asm("mov.b64 {%0, %1}, %2;" : "=f"(lo), "=f"(hi) : "l"(v));
}
__device__ __forceinline__ u64 mul2(u64 a, u64 b) {
    u64 d; asm("mul.rn.f32x2 %0, %1, %2;" : "=l"(d) : "l"(a), "l"(b)); return d;
}
__device__ __forceinline__ u64 fma2(u64 a, u64 b, u64 c) {
    u64 d; asm("fma.rn.f32x2 %0, %1, %2, %3;" : "=l"(d) : "l"(a), "l"(b), "l"(c)); return d;
}
__device__ __forceinline__ u64 add2(u64 a, u64 b) {
    u64 d; asm("add.rn.f32x2 %0, %1, %2;" : "=l"(d) : "l"(a), "l"(b)); return d;
}

__device__ __forceinline__ void vqc8(const float a[8], float z[8]) {
    float c[8];
#pragma unroll
    for (int w = 0; w < 8; w++) c[w] = __cosf(a[w]);
    float p = c[0];
#pragma unroll
    for (int k = 1; k < 8; k++) { p *= c[k]; z[k] = p; }
    float q = c[1];
#pragma unroll
    for (int w = 2; w < 8; w++) q *= c[w];
    z[0] = q;
}

// paired K/V smem layout: float index for (token k, dim d):
//   kp=k>>1, h=d>>2, dd=d&3:  kp*16 + h*8 + (dd>>1)*4 + (dd&1)*2 + (k&1)
// -> float4 #(kp*4 + h*2 + j) = (K[2kp][h4+2j], K[2kp+1][h4+2j],
//                                K[2kp][h4+2j+1], K[2kp+1][h4+2j+1])
__device__ __forceinline__ int kvidx(int k, int d) {
    return (k >> 1) * 16 + (d >> 2) * 8 + ((d & 2) << 1) + ((d & 1) << 1) + (k & 1);
}

__global__ void __launch_bounds__(512) fused_kernel(
    const float* __restrict__ x,
    const float* __restrict__ Wq, const float* __restrict__ Wk,
    const float* __restrict__ Wv, const float* __restrict__ Wc,
    const float* __restrict__ Wf,
    const float* __restrict__ w1, const float* __restrict__ b1,
    const float* __restrict__ w2, const float* __restrict__ b2,
    const float* __restrict__ g1, const float* __restrict__ be1,
    const float* __restrict__ g2, const float* __restrict__ be2,
    float* __restrict__ out)
{
    __shared__ float Ks[SSEQ * 8];
    __shared__ float Vs[SSEQ * 8];
    __shared__ float Qs[QH * 8];
    __shared__ float Ctx[QH * 8];
    __shared__ float Part[QH * 2 * 5];
    __shared__ float cw1[64], cw2[64];
    __shared__ float cb1[8], cb2[8], cwc[8], cwf[8];
    __shared__ float cg1[8], cbe1[8], cg2[8], cbe2[8];

    const int b   = blockIdx.x >> 1;
    const int qh  = blockIdx.x & 1;
    const int tid = threadIdx.x;

    // ---------------- phase 1: QKV + constant staging ----------------
    if (tid < 256) {
        const int t = tid;
        const float4* xt = (const float4*)(x + (size_t)(b * SSEQ + t) * EGS);
        float4 x0 = xt[0], x1 = xt[1];
        float xi[8] = {x0.x, x0.y, x0.z, x0.w, x1.x, x1.y, x1.z, x1.w};
        float a[8], z[8];
#pragma unroll
        for (int w = 0; w < 8; w++) a[w] = xi[w] + __ldg(Wk + w);
        vqc8(a, z);
#pragma unroll
        for (int d = 0; d < 8; d++) Ks[kvidx(t, d)] = z[d];
#pragma unroll
        for (int w = 0; w < 8; w++) a[w] = xi[w] + __ldg(Wv + w);
        vqc8(a, z);
#pragma unroll
        for (int d = 0; d < 8; d++) Vs[kvidx(t, d)] = z[d];
    } else if (tid < 384) {
        const int i = tid - 256;
        const float4* xt = (const float4*)(x + (size_t)(b * SSEQ + qh * QH + i) * EGS);
        float4 x0 = xt[0], x1 = xt[1];
        float xi[8] = {x0.x, x0.y, x0.z, x0.w, x1.x, x1.y, x1.z, x1.w};
        float a[8], z[8];
#pragma unroll
        for (int w = 0; w < 8; w++) a[w] = xi[w] + __ldg(Wq + w);
        vqc8(a, z);
#pragma unroll
        for (int d = 0; d < 8; d++) Qs[i * 8 + d] = z[d] * QSCALE;
    } else {
        const int j = tid - 384;  // 128 threads
        if (j < 64) { cw1[j] = w1[j]; cw2[j] = w2[j]; }
        if (j < 8) {
            cb1[j] = b1[j];  cb2[j] = b2[j];
            cwc[j] = Wc[j];  cwf[j] = Wf[j];
            cg1[j] = g1[j];  cbe1[j] = be1[j];
            cg2[j] = g2[j];  cbe2[j] = be2[j];
        }
    }
    __syncthreads();

    // ---------------- phase 2: attention (2 keys / iter, f32x2) ----------------
    {
        const int i  = tid & 127;          // local query
        const int h  = (tid >> 7) & 1;     // head
        const int kh = tid >> 8;           // k-half

        float4 qv = *(const float4*)&Qs[i * 8 + h * 4];
        u64 qp0 = pk2(qv.x, qv.x), qp1 = pk2(qv.y, qv.y);
        u64 qp2 = pk2(qv.z, qv.z), qp3 = pk2(qv.w, qv.w);

        const float4* K4 = (const float4*)Ks;
        const float4* V4 = (const float4*)Vs;

        u64 sum2 = 0ull, cp0 = 0ull, cp1 = 0ull, cp2 = 0ull, cp3 = 0ull;
        const int base = kh * 64;
#pragma unroll 4
        for (int kp = 0; kp < 64; kp++) {
            const int idx = (base + kp) * 4 + h * 2;
            float4 kf0 = K4[idx], kf1 = K4[idx + 1];
            u64 s2 = mul2(qp0, pk2(kf0.x, kf0.y));
            s2 = fma2(qp1, pk2(kf0.z, kf0.w), s2);
            s2 = fma2(qp2, pk2(kf1.x, kf1.y), s2);
            s2 = fma2(qp3, pk2(kf1.z, kf1.w), s2);
            float slo, shi; upk2(slo, shi, s2);
            float p0 = ex2f(slo), p1 = ex2f(shi);
            u64 pp = pk2(p0, p1);
            float4 vf0 = V4[idx], vf1 = V4[idx + 1];
            sum2 = add2(sum2, pp);
            cp0 = fma2(pp, pk2(vf0.x, vf0.y), cp0);
            cp1 = fma2(pp, pk2(vf0.z, vf0.w), cp1);
            cp2 = fma2(pp, pk2(vf1.x, vf1.y), cp2);
            cp3 = fma2(pp, pk2(vf1.z, vf1.w), cp3);
        }
        float sl, sh; upk2(sl, sh, sum2);
        float ssum = sl + sh;
        float c[4];
        { float l, hx; upk2(l, hx, cp0); c[0] = l + hx; }
        { float l, hx; upk2(l, hx, cp1); c[1] = l + hx; }
        { float l, hx; upk2(l, hx, cp2); c[2] = l + hx; }
        { float l, hx; upk2(l, hx, cp3); c[3] = l + hx; }

        if (kh == 1) {
            float* pr = &Part[(i * 2 + h) * 5];
            pr[0] = ssum; pr[1] = c[0]; pr[2] = c[1]; pr[3] = c[2]; pr[4] = c[3];
        }
        __syncthreads();
        if (kh == 0) {
            const float* pr = &Part[(i * 2 + h) * 5];
            ssum += pr[0];
            c[0] += pr[1]; c[1] += pr[2]; c[2] += pr[3]; c[3] += pr[4];
            float inv = __fdividef(1.f, ssum);
            float* cx = &Ctx[i * 8 + h * 4];
            cx[0] = c[0] * inv; cx[1] = c[1] * inv;
            cx[2] = c[2] * inv; cx[3] = c[3] * inv;
        }
        __syncthreads();
    }

    // ---------------- phase 3: tail for 128 local tokens ----------------
    if (tid < QH) {
        const int tok = b * SSEQ + qh * QH + tid;
        const float4* xt = (const float4*)(x + (size_t)tok * EGS);
        float4 x0 = xt[0], x1 = xt[1];
        float xi[8] = {x0.x, x0.y, x0.z, x0.w, x1.x, x1.y, x1.z, x1.w};

        float a[8], ao[8];
#pragma unroll
        for (int w = 0; w < 8; w++) a[w] = Ctx[tid * 8 + w] + cwc[w];
        vqc8(a, ao);

        float y[8], m = 0.f;
#pragma unroll
        for (int w = 0; w < 8; w++) { y[w] = xi[w] + ao[w]; m += y[w]; }
        m *= 0.125f;
        float var = 0.f;
#pragma unroll
        for (int w = 0; w < 8; w++) { float d = y[w] - m; var = fmaf(d, d, var); }
        var *= 0.125f;
        float r = rsqrtf(var + 1e-5f);
        float xn[8];
#pragma unroll
        for (int w = 0; w < 8; w++) xn[w] = fmaf((y[w] - m) * r, cg1[w], cbe1[w]);

        float hh[8];
#pragma unroll
        for (int i2 = 0; i2 < 8; i2++) {
            float s = cb1[i2];
#pragma unroll
            for (int j = 0; j < 8; j++) s = fmaf(xn[j], cw1[i2 * 8 + j], s);
            hh[i2] = s;
        }

        float hq[8];
#pragma unroll
        for (int w = 0; w < 8; w++) a[w] = hh[w] + cwf[w];
        vqc8(a, hq);

        float z[8], m2 = 0.f;
#pragma unroll
        for (int i2 = 0; i2 < 8; i2++) {
            float s = cb2[i2];
#pragma unroll
            for (int j = 0; j < 8; j++) s = fmaf(hq[j], cw2[i2 * 8 + j], s);
            z[i2] = xn[i2] + s;
            m2 += z[i2];
        }
        m2 *= 0.125f;
        float v2 = 0.f;
#pragma unroll
        for (int i2 = 0; i2 < 8; i2++) { float d = z[i2] - m2; v2 = fmaf(d, d, v2); }
        v2 *= 0.125f;
        float r2 = rsqrtf(v2 + 1e-5f);
        float o[8];
#pragma unroll
        for (int i2 = 0; i2 < 8; i2++) o[i2] = fmaf((z[i2] - m2) * r2, cg2[i2], cbe2[i2]);

        float4* op = (float4*)(out + (size_t)tok * EGS);
        op[0] = make_float4(o[0], o[1], o[2], o[3]);
        op[1] = make_float4(o[4], o[5], o[6], o[7]);
    }
}

extern "C" void kernel_launch(void* const* d_in, const int* in_sizes, int n_in,
                              void* d_out, int out_size)
{
    const float* x   = (const float*)d_in[0];
    const float* Wq  = (const float*)d_in[1];
    const float* Wk  = (const float*)d_in[2];
    const float* Wv  = (const float*)d_in[3];
    const float* Wc  = (const float*)d_in[4];
    const float* Wf  = (const float*)d_in[5];
    const float* w1  = (const float*)d_in[6];
    const float* b1  = (const float*)d_in[7];
    const float* w2  = (const float*)d_in[8];
    const float* b2  = (const float*)d_in[9];
    const float* g1  = (const float*)d_in[10];
    const float* be1 = (const float*)d_in[11];
    const float* g2  = (const float*)d_in[12];
    const float* be2 = (const float*)d_in[13];
    float* out = (float*)d_out;

    const int ntok = in_sizes[0] / EGS;   // B*S
    const int nb   = ntok / SSEQ;         // B

    fused_kernel<<<nb * 2, 512>>>(x, Wq, Wk, Wv, Wc, Wf, w1, b1, w2, b2,
                                  g1, be1, g2, be2, out);
}

// round 3
// speedup vs baseline: 1.4102x; 1.0569x over previous
#include <cuda_runtime.h>
#include <math.h>

// ---------------------------------------------------------------------------
// ViTBlockQuantum, fully fused. Analytic collapse of the 8-qubit VQC:
//   phi_w = in_w + theta_w;  z_k = prod_{w=0..k} cos(phi_w) (k>=1),
//   z_0 = prod_{w=1..7} cos(phi_w)
// One kernel: block = (batch, query-half), 1024 threads.
//   phase 1: K (thr 0-255), V (thr 256-511), Q (thr 512-639), consts (640+)
//   phase 2: attention, 4-way k-split, f32x2-packed (2 keys / iter)
//   phase 3: per-token tail
// ---------------------------------------------------------------------------

#define EGS 8
#define SSEQ 256
#define QH 128
// 0.5 * (1/sqrt(dk)=... dk=4 -> 0.5) * log2(e), folded into Q for ex2 softmax
#define QSCALE 0.72134752044448170368f

typedef unsigned long long u64;

__device__ __forceinline__ float ex2f(float x) {
    float y; asm("ex2.approx.ftz.f32 %0, %1;" : "=f"(y) : "f"(x)); return y;
}
__device__ __forceinline__ u64 pk2(float lo, float hi) {
    u64 r; asm("mov.b64 %0, {%1, %2};" : "=l"(r) : "f"(lo), "f"(hi)); return r;
}
__device__ __forceinline__ void upk2(float& lo, float& hi, u64 v) {
    asm("mov.b64 {%0, %1}, %2;" : "=f"(lo), "=f"(hi) : "l"(v));
}
__device__ __forceinline__ u64 mul2(u64 a, u64 b) {
    u64 d; asm("mul.rn.f32x2 %0, %1, %2;" : "=l"(d) : "l"(a), "l"(b)); return d;
}
__device__ __forceinline__ u64 fma2(u64 a, u64 b, u64 c) {
    u64 d; asm("fma.rn.f32x2 %0, %1, %2, %3;" : "=l"(d) : "l"(a), "l"(b), "l"(c)); return d;
}
__device__ __forceinline__ u64 add2(u64 a, u64 b) {
    u64 d; asm("add.rn.f32x2 %0, %1, %2;" : "=l"(d) : "l"(a), "l"(b)); return d;
}

__device__ __forceinline__ void vqc8(const float a[8], float z[8]) {
    float c[8];
#pragma unroll
    for (int w = 0; w < 8; w++) c[w] = __cosf(a[w]);
    float p = c[0];
#pragma unroll
    for (int k = 1; k < 8; k++) { p *= c[k]; z[k] = p; }
    float q = c[1];
#pragma unroll
    for (int w = 2; w < 8; w++) q *= c[w];
    z[0] = q;
}

// paired K/V smem layout (2 keys interleaved within float4s):
// float4 #(kp*4 + h*2 + j) = (K[2kp][h4+2j], K[2kp+1][h4+2j],
//                             K[2kp][h4+2j+1], K[2kp+1][h4+2j+1])
__device__ __forceinline__ int kvidx(int k, int d) {
    return (k >> 1) * 16 + (d >> 2) * 8 + ((d & 2) << 1) + ((d & 1) << 1) + (k & 1);
}

__global__ void __launch_bounds__(1024) fused_kernel(
    const float* __restrict__ x,
    const float* __restrict__ Wq, const float* __restrict__ Wk,
    const float* __restrict__ Wv, const float* __restrict__ Wc,
    const float* __restrict__ Wf,
    const float* __restrict__ w1, const float* __restrict__ b1,
    const float* __restrict__ w2, const float* __restrict__ b2,
    const float* __restrict__ g1, const float* __restrict__ be1,
    const float* __restrict__ g2, const float* __restrict__ be2,
    float* __restrict__ out)
{
    __shared__ float Ks[SSEQ * 8];
    __shared__ float Vs[SSEQ * 8];
    __shared__ float Qs[QH * 8];
    __shared__ float Ctx[QH * 8];
    __shared__ float Part[3 * QH * 2 * 5];   // partials for kh = 1..3
    __shared__ float cw1[64], cw2[64];
    __shared__ float cb1[8], cb2[8], cwc[8], cwf[8];
    __shared__ float cg1[8], cbe1[8], cg2[8], cbe2[8];

    const int b   = blockIdx.x >> 1;
    const int qh  = blockIdx.x & 1;
    const int tid = threadIdx.x;

    // ---------------- phase 1: QKV + constant staging (parallel groups) ------
    if (tid < 512) {
        // 0-255: K for token tid ; 256-511: V for token tid-256
        const int t = tid & 255;
        const int isV = tid >> 8;
        const float* W = isV ? Wv : Wk;
        const float4* xt = (const float4*)(x + (size_t)(b * SSEQ + t) * EGS);
        float4 x0 = xt[0], x1 = xt[1];
        float a[8], z[8];
        a[0] = x0.x + __ldg(W + 0); a[1] = x0.y + __ldg(W + 1);
        a[2] = x0.z + __ldg(W + 2); a[3] = x0.w + __ldg(W + 3);
        a[4] = x1.x + __ldg(W + 4); a[5] = x1.y + __ldg(W + 5);
        a[6] = x1.z + __ldg(W + 6); a[7] = x1.w + __ldg(W + 7);
        vqc8(a, z);
        float* dst = isV ? Vs : Ks;
#pragma unroll
        for (int d = 0; d < 8; d++) dst[kvidx(t, d)] = z[d];
    } else if (tid < 640) {
        const int i = tid - 512;
        const float4* xt = (const float4*)(x + (size_t)(b * SSEQ + qh * QH + i) * EGS);
        float4 x0 = xt[0], x1 = xt[1];
        float a[8], z[8];
        a[0] = x0.x + __ldg(Wq + 0); a[1] = x0.y + __ldg(Wq + 1);
        a[2] = x0.z + __ldg(Wq + 2); a[3] = x0.w + __ldg(Wq + 3);
        a[4] = x1.x + __ldg(Wq + 4); a[5] = x1.y + __ldg(Wq + 5);
        a[6] = x1.z + __ldg(Wq + 6); a[7] = x1.w + __ldg(Wq + 7);
        vqc8(a, z);
#pragma unroll
        for (int d = 0; d < 8; d++) Qs[i * 8 + d] = z[d] * QSCALE;
    } else {
        const int j = tid - 640;
        if (j < 64) { cw1[j] = w1[j]; cw2[j] = w2[j]; }
        else if (j < 72) {
            const int k = j - 64;
            cb1[k] = b1[k];  cb2[k] = b2[k];
            cwc[k] = Wc[k];  cwf[k] = Wf[k];
            cg1[k] = g1[k];  cbe1[k] = be1[k];
            cg2[k] = g2[k];  cbe2[k] = be2[k];
        }
    }
    __syncthreads();

    // ---------------- phase 2: attention (2 keys / iter, f32x2) --------------
    {
        const int i  = tid & 127;          // local query
        const int h  = (tid >> 7) & 1;     // head
        const int kh = tid >> 8;           // k-quarter (0..3)

        float4 qv = *(const float4*)&Qs[i * 8 + h * 4];
        u64 qp0 = pk2(qv.x, qv.x), qp1 = pk2(qv.y, qv.y);
        u64 qp2 = pk2(qv.z, qv.z), qp3 = pk2(qv.w, qv.w);

        const float4* K4 = (const float4*)Ks;
        const float4* V4 = (const float4*)Vs;

        u64 sum2 = 0ull, cp0 = 0ull, cp1 = 0ull, cp2 = 0ull, cp3 = 0ull;
        const int base = kh * 32;
#pragma unroll 4
        for (int kp = 0; kp < 32; kp++) {
            const int idx = (base + kp) * 4 + h * 2;
            float4 kf0 = K4[idx], kf1 = K4[idx + 1];
            u64 s2 = mul2(qp0, pk2(kf0.x, kf0.y));
            s2 = fma2(qp1, pk2(kf0.z, kf0.w), s2);
            s2 = fma2(qp2, pk2(kf1.x, kf1.y), s2);
            s2 = fma2(qp3, pk2(kf1.z, kf1.w), s2);
            float slo, shi; upk2(slo, shi, s2);
            float p0 = ex2f(slo), p1 = ex2f(shi);
            u64 pp = pk2(p0, p1);
            float4 vf0 = V4[idx], vf1 = V4[idx + 1];
            sum2 = add2(sum2, pp);
            cp0 = fma2(pp, pk2(vf0.x, vf0.y), cp0);
            cp1 = fma2(pp, pk2(vf0.z, vf0.w), cp1);
            cp2 = fma2(pp, pk2(vf1.x, vf1.y), cp2);
            cp3 = fma2(pp, pk2(vf1.z, vf1.w), cp3);
        }
        float sl, sh; upk2(sl, sh, sum2);
        float ssum = sl + sh;
        float c[4];
        { float l, hx; upk2(l, hx, cp0); c[0] = l + hx; }
        { float l, hx; upk2(l, hx, cp1); c[1] = l + hx; }
        { float l, hx; upk2(l, hx, cp2); c[2] = l + hx; }
        { float l, hx; upk2(l, hx, cp3); c[3] = l + hx; }

        if (kh != 0) {
            float* pr = &Part[(((kh - 1) << 8) + i * 2 + h) * 5];
            pr[0] = ssum; pr[1] = c[0]; pr[2] = c[1]; pr[3] = c[2]; pr[4] = c[3];
        }
        __syncthreads();
        if (kh == 0) {
#pragma unroll
            for (int r = 0; r < 3; r++) {
                const float* pr = &Part[((r << 8) + i * 2 + h) * 5];
                ssum += pr[0];
                c[0] += pr[1]; c[1] += pr[2]; c[2] += pr[3]; c[3] += pr[4];
            }
            float inv = __fdividef(1.f, ssum);
            float* cx = &Ctx[i * 8 + h * 4];
            cx[0] = c[0] * inv; cx[1] = c[1] * inv;
            cx[2] = c[2] * inv; cx[3] = c[3] * inv;
        }
        __syncthreads();
    }

    // ---------------- phase 3: tail for 128 local tokens ----------------
    if (tid < QH) {
        const int tok = b * SSEQ + qh * QH + tid;
        const float4* xt = (const float4*)(x + (size_t)tok * EGS);
        float4 x0 = xt[0], x1 = xt[1];
        float xi[8] = {x0.x, x0.y, x0.z, x0.w, x1.x, x1.y, x1.z, x1.w};

        float a[8], ao[8];
#pragma unroll
        for (int w = 0; w < 8; w++) a[w] = Ctx[tid * 8 + w] + cwc[w];
        vqc8(a, ao);

        float y[8], m = 0.f;
#pragma unroll
        for (int w = 0; w < 8; w++) { y[w] = xi[w] + ao[w]; m += y[w]; }
        m *= 0.125f;
        float var = 0.f;
#pragma unroll
        for (int w = 0; w < 8; w++) { float d = y[w] - m; var = fmaf(d, d, var); }
        var *= 0.125f;
        float r = rsqrtf(var + 1e-5f);
        float xn[8];
#pragma unroll
        for (int w = 0; w < 8; w++) xn[w] = fmaf((y[w] - m) * r, cg1[w], cbe1[w]);

        float hh[8];
#pragma unroll
        for (int i2 = 0; i2 < 8; i2++) {
            float s = cb1[i2];
#pragma unroll
            for (int j = 0; j < 8; j++) s = fmaf(xn[j], cw1[i2 * 8 + j], s);
            hh[i2] = s;
        }

        float hq[8];
#pragma unroll
        for (int w = 0; w < 8; w++) a[w] = hh[w] + cwf[w];
        vqc8(a, hq);

        float z[8], m2 = 0.f;
#pragma unroll
        for (int i2 = 0; i2 < 8; i2++) {
            float s = cb2[i2];
#pragma unroll
            for (int j = 0; j < 8; j++) s = fmaf(hq[j], cw2[i2 * 8 + j], s);
            z[i2] = xn[i2] + s;
            m2 += z[i2];
        }
        m2 *= 0.125f;
        float v2 = 0.f;
#pragma unroll
        for (int i2 = 0; i2 < 8; i2++) { float d = z[i2] - m2; v2 = fmaf(d, d, v2); }
        v2 *= 0.125f;
        float r2 = rsqrtf(v2 + 1e-5f);
        float o[8];
#pragma unroll
        for (int i2 = 0; i2 < 8; i2++) o[i2] = fmaf((z[i2] - m2) * r2, cg2[i2], cbe2[i2]);

        float4* op = (float4*)(out + (size_t)tok * EGS);
        op[0] = make_float4(o[0], o[1], o[2], o[3]);
        op[1] = make_float4(o[4], o[5], o[6], o[7]);
    }
}

extern "C" void kernel_launch(void* const* d_in, const int* in_sizes, int n_in,
                              void* d_out, int out_size)
{
    const float* x   = (const float*)d_in[0];
    const float* Wq  = (const float*)d_in[1];
    const float* Wk  = (const float*)d_in[2];
    const float* Wv  = (const float*)d_in[3];
    const float* Wc  = (const float*)d_in[4];
    const float* Wf  = (const float*)d_in[5];
    const float* w1  = (const float*)d_in[6];
    const float* b1  = (const float*)d_in[7];
    const float* w2  = (const float*)d_in[8];
    const float* b2  = (const float*)d_in[9];
    const float* g1  = (const float*)d_in[10];
    const float* be1 = (const float*)d_in[11];
    const float* g2  = (const float*)d_in[12];
    const float* be2 = (const float*)d_in[13];
    float* out = (float*)d_out;

    const int ntok = in_sizes[0] / EGS;   // B*S
    const int nb   = ntok / SSEQ;         // B

    fused_kernel<<<nb * 2, 1024>>>(x, Wq, Wk, Wv, Wc, Wf, w1, b1, w2, b2,
                                   g1, be1, g2, be2, out);
}